// round 1
// baseline (speedup 1.0000x reference)
#include <cuda_runtime.h>
#include <math.h>

// Fused FeedForward_denoise kernel.
// B=4, DIM=64, HID=128, H=W=256. Output fp32 [4,64,256,256].
//
// Tile: 16x16 output pixels per block, 256 threads (1 thread = 1 pixel).
// Per channel-pair (cp, cp+64), cp in 0..63:
//   Phase A: compute xc channels {3cp..3cp+2, 192+3cp..194+3cp} on the 20x20
//            halo region (zero outside image — conv zero-padding of xc).
//   B1: grouped 3x3 (w_dw1) for both channels -> gelu gate -> acc[0..31].
//   B2: grouped 3x3 (w_dw3a) on 18x18 region into smem.
//   B3: depthwise 3x3 (w_dw3b) -> gelu gate -> acc[32..63].
// Final: out = acc + b_out.

#define TILE 16

// shared memory offsets (in floats)
#define SM_SX     0          // 64*400  = 25600
#define SM_SPN    25600      // 2*400   = 800
#define SM_XC     26400      // 6*400   = 2400
#define SM_D3A    28800      // 2*324   = 648
#define SM_SWP    29448      // 6*64    = 384
#define SM_WOUT   29832      // 64*64   = 4096
#define SM_WDW1   33928      // 128*27  = 3456
#define SM_WDW3A  37384      // 128*27  = 3456
#define SM_WDW3B  40840      // 128*9   = 1152
#define SM_BDW1   41992      // 128
#define SM_BDW3A  42120      // 128
#define SM_BDW3B  42248      // 128
#define SM_BOUT   42376      // 64
#define SM_WPN    42440      // 128*2   = 256
#define SM_BPN    42696      // 128
#define SM_BIN    42824      // 256
#define SM_TOTAL  43080      // floats -> 172320 bytes

__device__ __forceinline__ float gelu_exact(float v) {
    return 0.5f * v * (1.0f + erff(v * 0.70710678118654752f));
}

__global__ void __launch_bounds__(256, 1)
ffn_fused_kernel(const float* __restrict__ x,
                 const float* __restrict__ pneff,
                 const float* __restrict__ w_in,  const float* __restrict__ b_in,
                 const float* __restrict__ w_pn,  const float* __restrict__ b_pn,
                 const float* __restrict__ w_dw1, const float* __restrict__ b_dw1,
                 const float* __restrict__ w_dw3a,const float* __restrict__ b_dw3a,
                 const float* __restrict__ w_dw3b,const float* __restrict__ b_dw3b,
                 const float* __restrict__ w_out, const float* __restrict__ b_out,
                 float* __restrict__ out)
{
    extern __shared__ float sm[];
    const int tid = threadIdx.x;
    const int bx0 = blockIdx.x * TILE;
    const int by0 = blockIdx.y * TILE;
    const int b   = blockIdx.z;

    // ---- stage weights/biases into shared ----
    for (int v = tid; v < 4096; v += 256) sm[SM_WOUT + v]  = w_out[v];
    for (int v = tid; v < 3456; v += 256) sm[SM_WDW1 + v]  = w_dw1[v];
    for (int v = tid; v < 3456; v += 256) sm[SM_WDW3A + v] = w_dw3a[v];
    for (int v = tid; v < 1152; v += 256) sm[SM_WDW3B + v] = w_dw3b[v];
    if (tid < 128) {
        sm[SM_BDW1  + tid] = b_dw1[tid];
        sm[SM_BDW3A + tid] = b_dw3a[tid];
        sm[SM_BDW3B + tid] = b_dw3b[tid];
        sm[SM_BPN   + tid] = b_pn[tid];
    }
    if (tid < 64) sm[SM_BOUT + tid] = b_out[tid];
    // w_pn (256) and b_in (256): one element per thread
    sm[SM_WPN + tid] = w_pn[tid];
    sm[SM_BIN + tid] = b_in[tid];

    // ---- stage x tile (20x20 halo, 64 channels) and pneff tile ----
    {
        const float* xb = x + (size_t)b * 64 * 65536;
        for (int c = 0; c < 64; ++c) {
            const float* xcp = xb + (size_t)c * 65536;
            for (int p = tid; p < 400; p += 256) {
                int ry = p / 20;
                int rx = p - ry * 20;
                int gy = by0 + ry - 2;
                int gx = bx0 + rx - 2;
                float vv = 0.0f;
                if ((unsigned)gy < 256u && (unsigned)gx < 256u)
                    vv = xcp[gy * 256 + gx];
                sm[SM_SX + c * 400 + p] = vv;
            }
        }
        const float* pnb = pneff + (size_t)b * 2 * 65536;
        for (int c = 0; c < 2; ++c) {
            const float* pcp = pnb + (size_t)c * 65536;
            for (int p = tid; p < 400; p += 256) {
                int ry = p / 20;
                int rx = p - ry * 20;
                int gy = by0 + ry - 2;
                int gx = bx0 + rx - 2;
                float vv = 0.0f;
                if ((unsigned)gy < 256u && (unsigned)gx < 256u)
                    vv = pcp[gy * 256 + gx];
                sm[SM_SPN + c * 400 + p] = vv;
            }
        }
    }

    float acc[64];
#pragma unroll
    for (int o = 0; o < 64; ++o) acc[o] = 0.0f;

    const int ty = tid >> 4;
    const int tx = tid & 15;

    for (int cp = 0; cp < 64; ++cp) {
        const int cA0 = 3 * cp;        // xc channels of group cp
        const int cB0 = 192 + 3 * cp;  // xc channels of group cp+64

        // stage per-pair 1x1 weights (xi channels only; pn uses SM_WPN)
        for (int idx = tid; idx < 384; idx += 256) {
            int j = idx >> 6;
            int k = idx & 63;
            int c = (j < 3) ? (cA0 + j) : (cB0 + (j - 3));
            if (c >= 128)
                sm[SM_SWP + idx] = w_in[(c - 128) * 64 + k];
        }
        __syncthreads();  // sync1: swpair ready; previous-iter readers done

        // ---- Phase A: 6 xc channels on 20x20 halo region ----
        for (int v = tid; v < 600; v += 256) {
            int j  = v / 100;             // 0..5
            int qp = (v - j * 100) * 4;   // base pixel of this quad
            int c  = (j < 3) ? (cA0 + j) : (cB0 + (j - 3));
            float4 r;
            if (c < 128) {
                // pn channel: 2-dot
                float w0 = sm[SM_WPN + 2 * c];
                float w1 = sm[SM_WPN + 2 * c + 1];
                float bb = sm[SM_BPN + c];
                float4 p0 = *(const float4*)(sm + SM_SPN + qp);
                float4 p1 = *(const float4*)(sm + SM_SPN + 400 + qp);
                r.x = fmaf(w0, p0.x, fmaf(w1, p1.x, bb));
                r.y = fmaf(w0, p0.y, fmaf(w1, p1.y, bb));
                r.z = fmaf(w0, p0.z, fmaf(w1, p1.z, bb));
                r.w = fmaf(w0, p0.w, fmaf(w1, p1.w, bb));
            } else {
                // xi channel: 64-dot against x tile
                float bb = sm[SM_BIN + (c - 128)];
                float4 a;
                a.x = bb; a.y = bb; a.z = bb; a.w = bb;
                const float* wr  = sm + SM_SWP + j * 64;
                const float* sxq = sm + SM_SX + qp;
#pragma unroll
                for (int k4 = 0; k4 < 16; ++k4) {
                    float4 w4 = *(const float4*)(wr + 4 * k4);
                    const float* sp = sxq + (4 * k4) * 400;
                    float4 s0 = *(const float4*)(sp);
                    float4 s1 = *(const float4*)(sp + 400);
                    float4 s2 = *(const float4*)(sp + 800);
                    float4 s3 = *(const float4*)(sp + 1200);
                    a.x = fmaf(w4.x, s0.x, a.x); a.y = fmaf(w4.x, s0.y, a.y);
                    a.z = fmaf(w4.x, s0.z, a.z); a.w = fmaf(w4.x, s0.w, a.w);
                    a.x = fmaf(w4.y, s1.x, a.x); a.y = fmaf(w4.y, s1.y, a.y);
                    a.z = fmaf(w4.y, s1.z, a.z); a.w = fmaf(w4.y, s1.w, a.w);
                    a.x = fmaf(w4.z, s2.x, a.x); a.y = fmaf(w4.z, s2.y, a.y);
                    a.z = fmaf(w4.z, s2.z, a.z); a.w = fmaf(w4.z, s2.w, a.w);
                    a.x = fmaf(w4.w, s3.x, a.x); a.y = fmaf(w4.w, s3.y, a.y);
                    a.z = fmaf(w4.w, s3.z, a.z); a.w = fmaf(w4.w, s3.w, a.w);
                }
                r = a;
            }
            // zero-mask out-of-image halo pixels (xc is zero-padded by conv)
#pragma unroll
            for (int e = 0; e < 4; ++e) {
                int p  = qp + e;
                int ry = p / 20;
                int rx = p - ry * 20;
                int gy = by0 + ry - 2;
                int gx = bx0 + rx - 2;
                float val = (e == 0) ? r.x : (e == 1) ? r.y : (e == 2) ? r.z : r.w;
                sm[SM_XC + j * 400 + p] =
                    ((unsigned)gy < 256u && (unsigned)gx < 256u) ? val : 0.0f;
            }
        }
        __syncthreads();  // sync2: xc ready

        // ---- B1: d1 pair, gate, accumulate out channels 0..31 ----
        {
            float d1a = sm[SM_BDW1 + cp];
            float d1b = sm[SM_BDW1 + cp + 64];
            const float* wA = sm + SM_WDW1 + cp * 27;
            const float* wB = sm + SM_WDW1 + (cp + 64) * 27;
#pragma unroll
            for (int j = 0; j < 3; ++j)
#pragma unroll
                for (int ky = 0; ky < 3; ++ky)
#pragma unroll
                    for (int kx = 0; kx < 3; ++kx) {
                        int xi_idx = (ty + 1 + ky) * 20 + (tx + 1 + kx);
                        int wi = j * 9 + ky * 3 + kx;
                        float xa = sm[SM_XC + j * 400 + xi_idx];
                        float xb = sm[SM_XC + (3 + j) * 400 + xi_idx];
                        d1a = fmaf(wA[wi], xa, d1a);
                        d1b = fmaf(wB[wi], xb, d1b);
                    }
            float g1 = gelu_exact(d1a) * d1b;
#pragma unroll
            for (int o = 0; o < 32; ++o)
                acc[o] = fmaf(sm[SM_WOUT + o * 64 + cp], g1, acc[o]);
        }

        // ---- B2: d3a on 18x18 region, both channels ----
        for (int v = tid; v < 648; v += 256) {
            int h = (v >= 324) ? 1 : 0;
            int p = v - h * 324;
            int qy = p / 18;
            int qx = p - qy * 18;
            int gy = by0 + qy - 1;
            int gx = bx0 + qx - 1;
            float r = 0.0f;
            if ((unsigned)gy < 256u && (unsigned)gx < 256u) {
                int ch = cp + h * 64;
                r = sm[SM_BDW3A + ch];
                const float* wd  = sm + SM_WDW3A + ch * 27;
                const float* xc0 = sm + SM_XC + h * 1200;  // 3 channels x 400
#pragma unroll
                for (int j = 0; j < 3; ++j)
#pragma unroll
                    for (int ky = 0; ky < 3; ++ky)
#pragma unroll
                        for (int kx = 0; kx < 3; ++kx)
                            r = fmaf(wd[j * 9 + ky * 3 + kx],
                                     xc0[j * 400 + (qy + ky) * 20 + (qx + kx)], r);
            }
            sm[SM_D3A + h * 324 + p] = r;
        }
        __syncthreads();  // sync3: d3a ready

        // ---- B3: depthwise 3x3 on d3a, gate, accumulate out channels 32..63 ----
        {
            float dA = sm[SM_BDW3B + cp];
            float dB = sm[SM_BDW3B + cp + 64];
            const float* wA = sm + SM_WDW3B + cp * 9;
            const float* wB = sm + SM_WDW3B + (cp + 64) * 9;
#pragma unroll
            for (int ky = 0; ky < 3; ++ky)
#pragma unroll
                for (int kx = 0; kx < 3; ++kx) {
                    int qi = (ty + ky) * 18 + (tx + kx);
                    float a0 = sm[SM_D3A + qi];
                    float a1 = sm[SM_D3A + 324 + qi];
                    dA = fmaf(wA[ky * 3 + kx], a0, dA);
                    dB = fmaf(wB[ky * 3 + kx], a1, dB);
                }
            float g2 = gelu_exact(dA) * dB;
#pragma unroll
            for (int o = 0; o < 32; ++o)
                acc[32 + o] = fmaf(sm[SM_WOUT + (32 + o) * 64 + cp], g2, acc[32 + o]);
        }
        __syncthreads();  // guard d3a/xc reuse in next pair (paired with sync1)
    }

    // ---- write output ----
    {
        float* ob = out + (size_t)b * 64 * 65536
                        + (size_t)(by0 + ty) * 256 + (bx0 + tx);
#pragma unroll
        for (int o = 0; o < 64; ++o)
            ob[(size_t)o * 65536] = acc[o] + sm[SM_BOUT + o];
    }
}

extern "C" void kernel_launch(void* const* d_in, const int* in_sizes, int n_in,
                              void* d_out, int out_size)
{
    (void)in_sizes; (void)n_in; (void)out_size;
    const float* x      = (const float*)d_in[0];
    const float* pneff  = (const float*)d_in[1];
    const float* w_in   = (const float*)d_in[2];
    const float* b_in   = (const float*)d_in[3];
    const float* w_pn   = (const float*)d_in[4];
    const float* b_pn   = (const float*)d_in[5];
    const float* w_dw1  = (const float*)d_in[6];
    const float* b_dw1  = (const float*)d_in[7];
    const float* w_dw3a = (const float*)d_in[8];
    const float* b_dw3a = (const float*)d_in[9];
    const float* w_dw3b = (const float*)d_in[10];
    const float* b_dw3b = (const float*)d_in[11];
    const float* w_out  = (const float*)d_in[12];
    const float* b_out  = (const float*)d_in[13];
    float* out = (float*)d_out;

    const size_t smem_bytes = SM_TOTAL * sizeof(float);
    cudaFuncSetAttribute(ffn_fused_kernel,
                         cudaFuncAttributeMaxDynamicSharedMemorySize,
                         (int)smem_bytes);

    dim3 grid(16, 16, 4);
    dim3 block(256);
    ffn_fused_kernel<<<grid, block, smem_bytes>>>(
        x, pneff, w_in, b_in, w_pn, b_pn, w_dw1, b_dw1,
        w_dw3a, b_dw3a, w_dw3b, b_dw3b, w_out, b_out, out);
}